// round 4
// baseline (speedup 1.0000x reference)
#include <cuda_runtime.h>
#include <math.h>

// Problem constants (match reference)
#define BB 32
#define NN 2048
#define DD 512
#define KK 256
#define NEG_SLOPE 0.01f

// Scratch (no device allocation allowed -> __device__ globals)
__device__ float g_vQp[BB * KK];     // vQ @ Wq + bq
__device__ float g_scores[BB * NN];  // pre-softmax scores
__device__ float g_pi[BB * NN];      // softmax probs
__device__ float g_t[BB * DD];       // pi @ vI

// ---------------------------------------------------------------------------
// Kernel 0: zero g_t (needed fresh every graph replay; attn kernel atomically
// accumulates into it)
// ---------------------------------------------------------------------------
__global__ void zero_t_kernel() {
    g_t[blockIdx.x * 512 + threadIdx.x] = 0.0f;
}

// ---------------------------------------------------------------------------
// Kernel 1: vQp[b,k] = sum_d vQ[b,d] * Wq[d,k] + bq[k]
// grid = B, block = K (=256)
// ---------------------------------------------------------------------------
__global__ void vqp_kernel(const float* __restrict__ vQ,
                           const float* __restrict__ Wq,
                           const float* __restrict__ bq) {
    int b = blockIdx.x;
    int k = threadIdx.x;  // 0..255
    __shared__ float sq[DD];
    sq[k]       = vQ[b * DD + k];
    sq[k + 256] = vQ[b * DD + 256 + k];
    __syncthreads();
    float acc = bq[k];
#pragma unroll 8
    for (int d = 0; d < DD; d++) acc = fmaf(sq[d], Wq[d * KK + k], acc);
    g_vQp[b * KK + k] = acc;
}

// ---------------------------------------------------------------------------
// Kernel 2 (dominant): fused scores GEMM.
// For each (b, 64-row n-tile): compute vIp tile = vI[b, rows, :] @ Wi  (64x256),
// epilogue: x = tile + vQp[b,:]; h = leaky_relu(x); scores = h . Wp
// Never materializes vIp to global memory.
//
// block = 256 threads. Micro-tile: warp w owns rows w*8..w*8+7 (all 256 cols
// spread over 32 lanes, 8 cols each) -> 8x8 fp32 accumulators per thread.
// A-frag reads are warp-broadcast LDS (conflict-free), B-frag reads are 2x
// LDS.128 per dd. ~97% of issue slots are FFMA.
// ---------------------------------------------------------------------------
#define BM 64   // n rows per block
#define BK 16   // d chunk

__global__ __launch_bounds__(256, 2)
void scores_kernel(const float* __restrict__ vI,
                   const float* __restrict__ Wi,
                   const float* __restrict__ Wp) {
    __shared__ float As[BK][BM + 4];   // transposed vI tile, rows 16B-aligned (68*4=272B)
    __shared__ float Bs[BK][KK];       // Wi chunk
    __shared__ float sh_vqp[KK];
    __shared__ float sh_wp[KK];

    const int b   = blockIdx.y;
    const int n0  = blockIdx.x * BM;
    const int tid = threadIdx.x;

    sh_vqp[tid] = g_vQp[b * KK + tid];
    sh_wp[tid]  = Wp[tid];

    const int warp = tid >> 5;        // 0..7 -> row group
    const int lane = tid & 31;        // col group
    const int r0 = warp * 8;
    const int c0 = lane * 8;

    float acc[8][8];
#pragma unroll
    for (int i = 0; i < 8; i++)
#pragma unroll
        for (int j = 0; j < 8; j++) acc[i][j] = 0.0f;

    const float* vIb = vI + ((size_t)b * NN + n0) * DD;

    // A-tile load mapping: one float4 per thread per chunk
    const int a_row = tid >> 2;            // 0..63
    const int a_seg = (tid & 3) * 4;       // 0,4,8,12
    // B-tile load mapping: 4 float4 per thread
    const int b_k  = (tid & 63) * 4;       // 0..252
    const int b_dd = tid >> 6;             // 0..3

    for (int d0 = 0; d0 < DD; d0 += BK) {
        __syncthreads();
        // Load A chunk [64 rows x 16 d] transposed into As[dd][row]
        float4 av = *reinterpret_cast<const float4*>(vIb + (size_t)a_row * DD + d0 + a_seg);
        As[a_seg + 0][a_row] = av.x;
        As[a_seg + 1][a_row] = av.y;
        As[a_seg + 2][a_row] = av.z;
        As[a_seg + 3][a_row] = av.w;
        // Load B chunk Wi[d0..d0+15][0..255]
#pragma unroll
        for (int i = 0; i < 4; i++) {
            int dd = b_dd + i * 4;
            *reinterpret_cast<float4*>(&Bs[dd][b_k]) =
                *reinterpret_cast<const float4*>(Wi + (size_t)(d0 + dd) * KK + b_k);
        }
        __syncthreads();

#pragma unroll
        for (int dd = 0; dd < BK; dd++) {
            float a[8], bb[8];
            // warp-uniform address -> broadcast, conflict-free
            float4 a0 = *reinterpret_cast<const float4*>(&As[dd][r0]);
            float4 a1 = *reinterpret_cast<const float4*>(&As[dd][r0 + 4]);
            a[0]=a0.x; a[1]=a0.y; a[2]=a0.z; a[3]=a0.w;
            a[4]=a1.x; a[5]=a1.y; a[6]=a1.z; a[7]=a1.w;
            float4 b0 = *reinterpret_cast<const float4*>(&Bs[dd][c0]);
            float4 b1 = *reinterpret_cast<const float4*>(&Bs[dd][c0 + 4]);
            bb[0]=b0.x; bb[1]=b0.y; bb[2]=b0.z; bb[3]=b0.w;
            bb[4]=b1.x; bb[5]=b1.y; bb[6]=b1.z; bb[7]=b1.w;
#pragma unroll
            for (int i = 0; i < 8; i++)
#pragma unroll
                for (int j = 0; j < 8; j++)
                    acc[i][j] = fmaf(a[i], bb[j], acc[i][j]);
        }
    }

    // Epilogue: +vQp, leaky-relu, dot with Wp, warp-reduce across cols
    float partial[8];
#pragma unroll
    for (int i = 0; i < 8; i++) {
        float s = 0.0f;
#pragma unroll
        for (int j = 0; j < 8; j++) {
            float x = acc[i][j] + sh_vqp[c0 + j];
            float h = x > 0.0f ? x : NEG_SLOPE * x;
            s = fmaf(h, sh_wp[c0 + j], s);
        }
        partial[i] = s;
    }
#pragma unroll
    for (int off = 16; off > 0; off >>= 1) {
#pragma unroll
        for (int i = 0; i < 8; i++)
            partial[i] += __shfl_xor_sync(0xffffffffu, partial[i], off);
    }
    if (lane == 0) {
#pragma unroll
        for (int i = 0; i < 8; i++)
            g_scores[(size_t)b * NN + n0 + r0 + i] = partial[i];
    }
}

// ---------------------------------------------------------------------------
// Kernel 3: softmax over N per batch. grid = B, block = 256.
// (bp[0] is a constant shift -> softmax-invariant; ignored.)
// ---------------------------------------------------------------------------
__global__ void softmax_kernel() {
    int b = blockIdx.x;
    int tid = threadIdx.x;
    __shared__ float red[256];
    const float* s = g_scores + (size_t)b * NN;
    float mx = -INFINITY;
    for (int i = tid; i < NN; i += 256) mx = fmaxf(mx, s[i]);
    red[tid] = mx;
    __syncthreads();
    for (int o = 128; o > 0; o >>= 1) {
        if (tid < o) red[tid] = fmaxf(red[tid], red[tid + o]);
        __syncthreads();
    }
    float m = red[0];
    __syncthreads();
    float sum = 0.0f;
    for (int i = tid; i < NN; i += 256) {
        float e = __expf(s[i] - m);
        g_pi[(size_t)b * NN + i] = e;
        sum += e;
    }
    red[tid] = sum;
    __syncthreads();
    for (int o = 128; o > 0; o >>= 1) {
        if (tid < o) red[tid] += red[tid + o];
        __syncthreads();
    }
    float inv = 1.0f / red[0];
    for (int i = tid; i < NN; i += 256) g_pi[(size_t)b * NN + i] *= inv;
}

// ---------------------------------------------------------------------------
// Kernel 4: t[b,d] = sum_n pi[b,n] * vI[b,n,d]
// grid = (8 n-chunks, B), block = 512 (one thread per d). Coalesced row reads.
// ---------------------------------------------------------------------------
__global__ void attn_kernel(const float* __restrict__ vI) {
    int b = blockIdx.y;
    int n0 = blockIdx.x * 256;
    int d = threadIdx.x;  // 0..511
    __shared__ float sp[256];
    if (d < 256) sp[d] = g_pi[(size_t)b * NN + n0 + d];
    __syncthreads();
    const float* base = vI + ((size_t)b * NN + n0) * DD + d;
    float acc = 0.0f;
#pragma unroll 4
    for (int n = 0; n < 256; n++) acc = fmaf(sp[n], base[(size_t)n * DD], acc);
    atomicAdd(&g_t[b * DD + d], acc);
}

// ---------------------------------------------------------------------------
// Kernel 5: out[b,k] = sum_d t[b,d] * Wi[d,k] + vQp[b,k]
// grid = B, block = K (=256)
// ---------------------------------------------------------------------------
__global__ void out_kernel(const float* __restrict__ Wi, float* __restrict__ out) {
    int b = blockIdx.x;
    int k = threadIdx.x;
    __shared__ float st[DD];
    st[k]       = g_t[b * DD + k];
    st[k + 256] = g_t[b * DD + 256 + k];
    __syncthreads();
    float acc = g_vQp[b * KK + k];
#pragma unroll 8
    for (int d = 0; d < DD; d++) acc = fmaf(st[d], Wi[d * KK + k], acc);
    out[b * KK + k] = acc;
}

// ---------------------------------------------------------------------------
// Launch. Inputs (metadata order): vI, vQ, Wi, Wq, bq, Wp, bp
// ---------------------------------------------------------------------------
extern "C" void kernel_launch(void* const* d_in, const int* in_sizes, int n_in,
                              void* d_out, int out_size) {
    const float* vI = (const float*)d_in[0];
    const float* vQ = (const float*)d_in[1];
    const float* Wi = (const float*)d_in[2];
    const float* Wq = (const float*)d_in[3];
    const float* bq = (const float*)d_in[4];
    const float* Wp = (const float*)d_in[5];
    // bp (d_in[6]) shifts scores by a constant -> softmax-invariant; unused.
    float* out = (float*)d_out;

    zero_t_kernel<<<BB, 512>>>();
    vqp_kernel<<<BB, 256>>>(vQ, Wq, bq);
    {
        dim3 grid(NN / BM, BB);  // 32 x 32
        scores_kernel<<<grid, 256>>>(vI, Wi, Wp);
    }
    softmax_kernel<<<BB, 256>>>();
    {
        dim3 grid(NN / 256, BB);  // 8 x 32
        attn_kernel<<<grid, 512>>>(vI);
    }
    out_kernel<<<BB, 256>>>(Wi, out);
}

// round 6
// speedup vs baseline: 1.9364x; 1.9364x over previous
#include <cuda_runtime.h>
#include <math.h>
#include <stdint.h>

// Problem constants
#define BB 32
#define NN 2048
#define DD 512
#define KK 256
#define NEG_SLOPE 0.01f

// Scratch (__device__ globals; no allocation allowed)
__device__ float g_vQp[BB * KK];     // vQ @ Wq + bq
__device__ float g_scores[BB * NN];  // pre-softmax scores
__device__ float g_pi[BB * NN];      // softmax probs
__device__ float g_t[BB * DD];       // pi @ vI
__device__ float g_WiT[KK * DD];     // Wi transposed [k][d], tf32(rna)-rounded

// ---------------------------------------------------------------------------
// Helpers
// ---------------------------------------------------------------------------
__device__ __forceinline__ uint32_t smem_u32(const void* p) {
    uint32_t a;
    asm("{ .reg .u64 t; cvta.to.shared.u64 t, %1; cvt.u32.u64 %0, t; }"
        : "=r"(a) : "l"(p));
    return a;
}
__device__ __forceinline__ uint32_t f2tf32(float f) {
    uint32_t r;
    asm("cvt.rna.tf32.f32 %0, %1;" : "=r"(r) : "f"(f));
    return r;
}
__device__ __forceinline__ void cp16(uint32_t smem_addr, const void* gptr) {
    asm volatile("cp.async.cg.shared.global [%0], [%1], 16;"
                 :: "r"(smem_addr), "l"(gptr) : "memory");
}
#define CP_COMMIT() asm volatile("cp.async.commit_group;" ::: "memory")
#define CP_WAIT(n)  asm volatile("cp.async.wait_group %0;" :: "n"(n) : "memory")

// m16n8k8 tf32 MMA (base-target PTX, works on sm_103 without 'a')
__device__ __forceinline__ void mma_tf32(float* d,
                                         uint32_t a0, uint32_t a1,
                                         uint32_t a2, uint32_t a3,
                                         uint32_t b0, uint32_t b1) {
    asm volatile(
        "mma.sync.aligned.m16n8k8.row.col.f32.tf32.tf32.f32 "
        "{%0,%1,%2,%3}, {%4,%5,%6,%7}, {%8,%9}, {%0,%1,%2,%3};"
        : "+f"(d[0]), "+f"(d[1]), "+f"(d[2]), "+f"(d[3])
        : "r"(a0), "r"(a1), "r"(a2), "r"(a3), "r"(b0), "r"(b1));
}

// ---------------------------------------------------------------------------
// Kernel 0: zero g_t
// ---------------------------------------------------------------------------
__global__ void zero_t_kernel() { g_t[blockIdx.x * 512 + threadIdx.x] = 0.0f; }

// ---------------------------------------------------------------------------
// Kernel 0b: WiT[k][d] = tf32_rna(Wi[d][k])
// ---------------------------------------------------------------------------
__global__ void transpose_wi_kernel(const float* __restrict__ Wi) {
    __shared__ float t[32][33];
    int d0 = blockIdx.x * 32, k0 = blockIdx.y * 32;
    t[threadIdx.y][threadIdx.x] = Wi[(d0 + threadIdx.y) * KK + (k0 + threadIdx.x)];
    __syncthreads();
    uint32_t v = f2tf32(t[threadIdx.x][threadIdx.y]);
    g_WiT[(size_t)(k0 + threadIdx.y) * DD + d0 + threadIdx.x] = __uint_as_float(v);
}

// ---------------------------------------------------------------------------
// Kernel 1: vQp = vQ @ Wq + bq
// ---------------------------------------------------------------------------
__global__ void vqp_kernel(const float* __restrict__ vQ,
                           const float* __restrict__ Wq,
                           const float* __restrict__ bq) {
    int b = blockIdx.x;
    int k = threadIdx.x;
    __shared__ float sq[DD];
    sq[k]       = vQ[b * DD + k];
    sq[k + 256] = vQ[b * DD + 256 + k];
    __syncthreads();
    float acc = bq[k];
#pragma unroll 8
    for (int d = 0; d < DD; d++) acc = fmaf(sq[d], Wq[d * KK + k], acc);
    g_vQp[b * KK + k] = acc;
}

// ---------------------------------------------------------------------------
// Kernel 2 (dominant): fused scores GEMM on the tensor pipe (mma.sync tf32).
// Per CTA: 64 tokens x 256 features, K=512 in 16 chunks of 32, cp.async
// double buffer. Warp w: row strip (w>>1)*16, column half (w&1)*128.
// Epilogue fuses +vQp, leaky-relu, dot with Wp -> g_scores only.
// Smem rows padded to 36 floats -> conflict-free STS + LDS frag reads.
// ---------------------------------------------------------------------------
#define M_TILE 64
#define KC 32
#define NCHUNK (DD / KC)          // 16
#define PAD 36                    // padded row stride in floats
#define A_FLOATS (M_TILE * PAD)   // 2304
#define B_FLOATS (KK * PAD)       // 9216
#define STG_FLOATS (A_FLOATS + B_FLOATS)         // 11520
#define SCORES_SMEM (2 * STG_FLOATS * 4)         // 92160 bytes

__global__ __launch_bounds__(256, 1)
void scores_mma_kernel(const float* __restrict__ vI,
                       const float* __restrict__ Wp) {
    extern __shared__ float smem[];
    __shared__ float svqp[KK];
    __shared__ float swp[KK];
    __shared__ float sred[2][M_TILE];

    const int tid  = threadIdx.x;
    const int lane = tid & 31;
    const int wid  = tid >> 5;
    const int b    = blockIdx.y;
    const int n0   = blockIdx.x * M_TILE;

    svqp[tid] = g_vQp[b * KK + tid];
    swp[tid]  = Wp[tid];

    // ---- async-copy source/dest mapping (16B quads) ----
    // A: 64 rows x 32 floats = 512 quads; thread t -> quads t and t+256
    const int rowA = tid >> 3;          // 0..31 (second quad: +32)
    const int iA   = (tid & 7) * 4;     // float offset in row
    const float* srcA0 = vI + ((size_t)b * NN + n0 + rowA) * DD + iA;
    const float* srcA1 = srcA0 + (size_t)32 * DD;
    // B: 256 cols x 32 floats = 2048 quads; thread t -> cols (t>>3)+32r
    const int colB = tid >> 3;          // base col (r adds 32)
    const int iB   = (tid & 7) * 4;
    const float* srcB = g_WiT + (size_t)colB * DD + iB;

    const uint32_t smem_base = smem_u32(smem);
    const uint32_t dstA0 = smem_base + (rowA * PAD + iA) * 4;
    const uint32_t dstA1 = dstA0 + 32 * PAD * 4;
    const uint32_t dstB0 = smem_base + (A_FLOATS + colB * PAD + iB) * 4;
    const uint32_t stg_bytes = STG_FLOATS * 4;

    // ---- fragment read offsets ----
    const int strip = wid >> 1;           // 0..3  (rows strip*16..+15)
    const int half  = wid & 1;            // 0..1  (cols half*128..+127)
    const int offA  = (strip * 16 + (lane >> 2)) * PAD + (lane & 3);
    const int offB  = (half * 128 + (lane >> 2)) * PAD + (lane & 3);

    float acc[16][4];
#pragma unroll
    for (int j = 0; j < 16; j++)
#pragma unroll
        for (int e = 0; e < 4; e++) acc[j][e] = 0.0f;

    // ---- prefetch chunk 0 into stage 0 ----
    {
        cp16(dstA0, srcA0);
        cp16(dstA1, srcA1);
#pragma unroll
        for (int r = 0; r < 8; r++)
            cp16(dstB0 + r * 32 * PAD * 4, srcB + (size_t)r * 32 * DD);
        CP_COMMIT();
    }

    for (int c = 0; c < NCHUNK; c++) {
        const int s = c & 1;
        if (c < NCHUNK - 1) {
            const int d0 = (c + 1) * KC;
            const uint32_t so = ((c + 1) & 1) * stg_bytes;
            cp16(dstA0 + so, srcA0 + d0);
            cp16(dstA1 + so, srcA1 + d0);
#pragma unroll
            for (int r = 0; r < 8; r++)
                cp16(dstB0 + so + r * 32 * PAD * 4,
                     srcB + (size_t)r * 32 * DD + d0);
            CP_COMMIT();
            CP_WAIT(1);
        } else {
            CP_WAIT(0);
        }
        __syncthreads();

        const float* As = smem + s * STG_FLOATS;
        const float* Bs = As + A_FLOATS;

#pragma unroll
        for (int ks = 0; ks < 4; ks++) {
            const int k0 = ks * 8;
            uint32_t a0 = f2tf32(As[offA + k0]);
            uint32_t a1 = f2tf32(As[offA + k0 + 8 * PAD]);
            uint32_t a2 = f2tf32(As[offA + k0 + 4]);
            uint32_t a3 = f2tf32(As[offA + k0 + 8 * PAD + 4]);
#pragma unroll
            for (int j = 0; j < 16; j++) {
                uint32_t b0 = __float_as_uint(Bs[offB + j * 8 * PAD + k0]);
                uint32_t b1 = __float_as_uint(Bs[offB + j * 8 * PAD + k0 + 4]);
                mma_tf32(acc[j], a0, a1, a2, a3, b0, b1);
            }
        }
        __syncthreads();
    }

    // ---- epilogue: +vQp, leaky-relu, dot with Wp ----
    float pl = 0.0f, ph = 0.0f;   // rows strip*16+(lane>>2) and +8
#pragma unroll
    for (int j = 0; j < 16; j++) {
        const int cb = half * 128 + j * 8 + 2 * (lane & 3);
#pragma unroll
        for (int e = 0; e < 2; e++) {
            const float vq = svqp[cb + e];
            const float wp = swp[cb + e];
            float x = acc[j][e] + vq;
            float h = x > 0.0f ? x : NEG_SLOPE * x;
            pl = fmaf(h, wp, pl);
            x = acc[j][2 + e] + vq;
            h = x > 0.0f ? x : NEG_SLOPE * x;
            ph = fmaf(h, wp, ph);
        }
    }
    pl += __shfl_xor_sync(0xffffffffu, pl, 1);
    pl += __shfl_xor_sync(0xffffffffu, pl, 2);
    ph += __shfl_xor_sync(0xffffffffu, ph, 1);
    ph += __shfl_xor_sync(0xffffffffu, ph, 2);
    if ((lane & 3) == 0) {
        sred[half][strip * 16 + (lane >> 2)]     = pl;
        sred[half][strip * 16 + 8 + (lane >> 2)] = ph;
    }
    __syncthreads();
    if (tid < M_TILE)
        g_scores[(size_t)b * NN + n0 + tid] = sred[0][tid] + sred[1][tid];
}

// ---------------------------------------------------------------------------
// Kernel 3: softmax over N per batch (bp is softmax-invariant; ignored)
// ---------------------------------------------------------------------------
__global__ void softmax_kernel() {
    int b = blockIdx.x;
    int tid = threadIdx.x;
    __shared__ float red[256];
    const float* s = g_scores + (size_t)b * NN;
    float mx = -INFINITY;
    for (int i = tid; i < NN; i += 256) mx = fmaxf(mx, s[i]);
    red[tid] = mx;
    __syncthreads();
    for (int o = 128; o > 0; o >>= 1) {
        if (tid < o) red[tid] = fmaxf(red[tid], red[tid + o]);
        __syncthreads();
    }
    float m = red[0];
    __syncthreads();
    float sum = 0.0f;
    for (int i = tid; i < NN; i += 256) {
        float e = __expf(s[i] - m);
        g_pi[(size_t)b * NN + i] = e;
        sum += e;
    }
    red[tid] = sum;
    __syncthreads();
    for (int o = 128; o > 0; o >>= 1) {
        if (tid < o) red[tid] += red[tid + o];
        __syncthreads();
    }
    float inv = 1.0f / red[0];
    for (int i = tid; i < NN; i += 256) g_pi[(size_t)b * NN + i] *= inv;
}

// ---------------------------------------------------------------------------
// Kernel 4: t[b,d] = sum_n pi[b,n] * vI[b,n,d]
// ---------------------------------------------------------------------------
__global__ void attn_kernel(const float* __restrict__ vI) {
    int b = blockIdx.y;
    int n0 = blockIdx.x * 256;
    int d = threadIdx.x;
    __shared__ float sp[256];
    if (d < 256) sp[d] = g_pi[(size_t)b * NN + n0 + d];
    __syncthreads();
    const float* base = vI + ((size_t)b * NN + n0) * DD + d;
    float acc = 0.0f;
#pragma unroll 4
    for (int n = 0; n < 256; n++) acc = fmaf(sp[n], base[(size_t)n * DD], acc);
    atomicAdd(&g_t[b * DD + d], acc);
}

// ---------------------------------------------------------------------------
// Kernel 5: out[b,k] = sum_d t[b,d] * Wi[d,k] + vQp[b,k]  (full-fp32 Wi)
// ---------------------------------------------------------------------------
__global__ void out_kernel(const float* __restrict__ Wi, float* __restrict__ out) {
    int b = blockIdx.x;
    int k = threadIdx.x;
    __shared__ float st[DD];
    st[k]       = g_t[b * DD + k];
    st[k + 256] = g_t[b * DD + 256 + k];
    __syncthreads();
    float acc = g_vQp[b * KK + k];
#pragma unroll 8
    for (int d = 0; d < DD; d++) acc = fmaf(st[d], Wi[d * KK + k], acc);
    out[b * KK + k] = acc;
}

// ---------------------------------------------------------------------------
// Launch. Inputs: vI, vQ, Wi, Wq, bq, Wp, bp
// ---------------------------------------------------------------------------
extern "C" void kernel_launch(void* const* d_in, const int* in_sizes, int n_in,
                              void* d_out, int out_size) {
    const float* vI = (const float*)d_in[0];
    const float* vQ = (const float*)d_in[1];
    const float* Wi = (const float*)d_in[2];
    const float* Wq = (const float*)d_in[3];
    const float* bq = (const float*)d_in[4];
    const float* Wp = (const float*)d_in[5];
    // bp shifts scores uniformly -> softmax-invariant; unused.
    float* out = (float*)d_out;

    cudaFuncSetAttribute(scores_mma_kernel,
                         cudaFuncAttributeMaxDynamicSharedMemorySize, SCORES_SMEM);

    zero_t_kernel<<<BB, 512>>>();
    {
        dim3 grid(DD / 32, KK / 32);
        dim3 blk(32, 32);
        transpose_wi_kernel<<<grid, blk>>>(Wi);
    }
    vqp_kernel<<<BB, 256>>>(vQ, Wq, bq);
    {
        dim3 grid(NN / M_TILE, BB);  // 32 x 32 = 1024 CTAs
        scores_mma_kernel<<<grid, 256, SCORES_SMEM>>>(vI, Wp);
    }
    softmax_kernel<<<BB, 256>>>();
    {
        dim3 grid(NN / 256, BB);
        attn_kernel<<<grid, 512>>>(vI);
    }
    out_kernel<<<BB, 256>>>(Wi, out);
}

// round 7
// speedup vs baseline: 2.7290x; 1.4093x over previous
#include <cuda_runtime.h>
#include <cuda_bf16.h>
#include <math.h>
#include <stdint.h>

// Problem constants
#define BB 32
#define NN 2048
#define DD 512
#define KK 256
#define NEG_SLOPE 0.01f

// Scratch (__device__ globals; no allocation allowed)
__device__ float g_vQp[BB * KK];                 // vQ @ Wq + bq
__device__ float g_scores[BB * NN];              // pre-softmax scores
__device__ float g_pi[BB * NN];                  // softmax probs
__device__ float g_t[BB * DD];                   // pi @ vI
__device__ __nv_bfloat16 g_WiTbf[KK * DD];       // Wi^T [k][d] in bf16

// ---------------------------------------------------------------------------
// Helpers
// ---------------------------------------------------------------------------
__device__ __forceinline__ uint32_t smem_u32(const void* p) {
    uint32_t a;
    asm("{ .reg .u64 t; cvta.to.shared.u64 t, %1; cvt.u32.u64 %0, t; }"
        : "=r"(a) : "l"(p));
    return a;
}
__device__ __forceinline__ uint32_t pack_bf16(float lo, float hi) {
    uint32_t r;
    asm("cvt.rn.bf16x2.f32 %0, %1, %2;" : "=r"(r) : "f"(hi), "f"(lo));
    return r;
}
__device__ __forceinline__ void cp16(uint32_t smem_addr, const void* gptr) {
    asm volatile("cp.async.cg.shared.global [%0], [%1], 16;"
                 :: "r"(smem_addr), "l"(gptr) : "memory");
}
#define CP_COMMIT() asm volatile("cp.async.commit_group;" ::: "memory")
#define CP_WAIT(n)  asm volatile("cp.async.wait_group %0;" :: "n"(n) : "memory")

__device__ __forceinline__ void ldsm4(uint32_t& r0, uint32_t& r1,
                                      uint32_t& r2, uint32_t& r3, uint32_t addr) {
    asm volatile("ldmatrix.sync.aligned.m8n8.x4.shared.b16 {%0,%1,%2,%3}, [%4];"
                 : "=r"(r0), "=r"(r1), "=r"(r2), "=r"(r3) : "r"(addr));
}
// m16n8k16 bf16 MMA (base-target PTX, sm_80+)
__device__ __forceinline__ void mma_bf16(float* d,
                                         uint32_t a0, uint32_t a1,
                                         uint32_t a2, uint32_t a3,
                                         uint32_t b0, uint32_t b1) {
    asm volatile(
        "mma.sync.aligned.m16n8k16.row.col.f32.bf16.bf16.f32 "
        "{%0,%1,%2,%3}, {%4,%5,%6,%7}, {%8,%9}, {%0,%1,%2,%3};"
        : "+f"(d[0]), "+f"(d[1]), "+f"(d[2]), "+f"(d[3])
        : "r"(a0), "r"(a1), "r"(a2), "r"(a3), "r"(b0), "r"(b1));
}

// ---------------------------------------------------------------------------
// Kernel 0b: WiTbf[k][d] = bf16(Wi[d][k])
// ---------------------------------------------------------------------------
__global__ void transpose_wi_kernel(const float* __restrict__ Wi) {
    __shared__ float t[32][33];
    int d0 = blockIdx.x * 32, k0 = blockIdx.y * 32;
    t[threadIdx.y][threadIdx.x] = Wi[(d0 + threadIdx.y) * KK + (k0 + threadIdx.x)];
    __syncthreads();
    g_WiTbf[(size_t)(k0 + threadIdx.y) * DD + d0 + threadIdx.x] =
        __float2bfloat16_rn(t[threadIdx.x][threadIdx.y]);
}

// ---------------------------------------------------------------------------
// Kernel 1: vQp = vQ @ Wq + bq   (also zeroes g_t)
// ---------------------------------------------------------------------------
__global__ void vqp_kernel(const float* __restrict__ vQ,
                           const float* __restrict__ Wq,
                           const float* __restrict__ bq) {
    int b = blockIdx.x;
    int k = threadIdx.x;
    g_t[b * DD + k] = 0.0f;
    g_t[b * DD + 256 + k] = 0.0f;
    __shared__ float sq[DD];
    sq[k]       = vQ[b * DD + k];
    sq[k + 256] = vQ[b * DD + 256 + k];
    __syncthreads();
    float acc = bq[k];
#pragma unroll 8
    for (int d = 0; d < DD; d++) acc = fmaf(sq[d], Wq[d * KK + k], acc);
    g_vQp[b * KK + k] = acc;
}

// ---------------------------------------------------------------------------
// Kernel 2 (dominant): fused scores GEMM, bf16 mma.sync + ldmatrix.
// Per CTA: 128 tokens x 256 feats, K=512 in 16 chunks of 32.
// 512 threads, 16 warps: warp w -> row strip (w>>1)*16, col half (w&1)*128.
// A (vI): LDG fp32 -> cvt bf16 -> STS, double-buffered under MMA.
// B (WiTbf): cp.async double buffer.
// Smem rows 40 bf16 (80B): every ldmatrix phase covers all 32 banks once.
// Epilogue fuses +vQp, leaky-relu, dot(Wp) -> g_scores only.
// ---------------------------------------------------------------------------
#define M_TILE 128
#define KC 32
#define NCH (DD / KC)               // 16
#define ASTRIDE 40                  // bf16 elems per smem row (80 B)
#define A_BF (M_TILE * ASTRIDE)     // 5120 bf16
#define B_BF (KK * ASTRIDE)         // 10240 bf16
#define STG_BF (A_BF + B_BF)        // 15360 bf16 = 30720 B
#define SCORES_SMEM (2 * STG_BF * 2)  // 61440 bytes

__global__ __launch_bounds__(512, 1)
void scores_mma_kernel(const float* __restrict__ vI,
                       const float* __restrict__ Wp) {
    extern __shared__ __nv_bfloat16 smem[];
    __shared__ float svqp[KK];
    __shared__ float swp[KK];
    __shared__ float sred[2][M_TILE];

    const int tid  = threadIdx.x;
    const int lane = tid & 31;
    const int wid  = tid >> 5;
    const int b    = blockIdx.y;
    const int n0   = blockIdx.x * M_TILE;

    if (tid < KK) {
        svqp[tid] = g_vQp[b * KK + tid];
        swp[tid]  = Wp[tid];
    }

    const uint32_t sb = smem_u32(smem);
    const uint32_t stg_bytes = STG_BF * 2;

    // ---- A producer mapping: 1024 float4-quads/chunk, 2 per thread ----
    const int aq0 = tid;              // quads tid and tid+512
    const int rowA0 = aq0 >> 3, segA0 = aq0 & 7;
    const int aq1 = tid + 512;
    const int rowA1 = aq1 >> 3, segA1 = aq1 & 7;
    const float* srcA0 = vI + ((size_t)b * NN + n0 + rowA0) * DD + segA0 * 4;
    const float* srcA1 = vI + ((size_t)b * NN + n0 + rowA1) * DD + segA1 * 4;
    const uint32_t dstA0 = sb + rowA0 * 80 + segA0 * 8;
    const uint32_t dstA1 = sb + rowA1 * 80 + segA1 * 8;

    // ---- B producer mapping: 1024 16B-quads/chunk, 2 per thread ----
    const int bq0 = tid;
    const int colB0 = bq0 >> 2, kqB0 = bq0 & 3;
    const int bq1 = tid + 512;
    const int colB1 = bq1 >> 2, kqB1 = bq1 & 3;
    const __nv_bfloat16* srcB0 = g_WiTbf + (size_t)colB0 * DD + kqB0 * 8;
    const __nv_bfloat16* srcB1 = g_WiTbf + (size_t)colB1 * DD + kqB1 * 8;
    const uint32_t dstB0 = sb + A_BF * 2 + colB0 * 80 + kqB0 * 16;
    const uint32_t dstB1 = sb + A_BF * 2 + colB1 * 80 + kqB1 * 16;

    // ---- fragment addresses ----
    const int strip = wid >> 1;       // 0..7
    const int half  = wid & 1;        // 0..1
    // A ldmatrix: tiles (m0-7,k0-7),(m8-15,k0-7),(m0-7,k8-15),(m8-15,k8-15)
    const uint32_t addrA_base =
        sb + (strip * 16 + (lane & 15)) * 80 + ((lane >> 4) & 1) * 16;
    // B ldmatrix per p: tiles (n0-7,k0-7),(n0-7,k8-15),(n8-15,k0-7),(n8-15,k8-15)
    const uint32_t addrB_base =
        sb + A_BF * 2 +
        (half * 128 + (lane & 7) + ((lane >> 4) & 1) * 8) * 80 +
        ((lane >> 3) & 1) * 16;

    float acc[16][4];
#pragma unroll
    for (int j = 0; j < 16; j++)
#pragma unroll
        for (int e = 0; e < 4; e++) acc[j][e] = 0.0f;

    // ---- prologue: fill stage 0 ----
    {
        float4 v0 = *(const float4*)srcA0;
        float4 v1 = *(const float4*)srcA1;
        uint2 p0 = make_uint2(pack_bf16(v0.x, v0.y), pack_bf16(v0.z, v0.w));
        uint2 p1 = make_uint2(pack_bf16(v1.x, v1.y), pack_bf16(v1.z, v1.w));
        *(uint2*)((char*)smem + (dstA0 - sb)) = p0;
        *(uint2*)((char*)smem + (dstA1 - sb)) = p1;
        cp16(dstB0, srcB0);
        cp16(dstB1, srcB1);
        CP_COMMIT();
        CP_WAIT(0);
    }
    __syncthreads();

    for (int c = 0; c < NCH; c++) {
        const int st = c & 1;
        const uint32_t so = st * stg_bytes;
        const uint32_t so_n = (st ^ 1) * stg_bytes;

        float4 pa0, pa1;
        const bool pf = (c + 1 < NCH);
        if (pf) {
            const int d0 = (c + 1) * KC;
            pa0 = *(const float4*)(srcA0 + d0);
            pa1 = *(const float4*)(srcA1 + d0);
            cp16(dstB0 + so_n, srcB0 + d0);
            cp16(dstB1 + so_n, srcB1 + d0);
            CP_COMMIT();
        }

        // ---- MMA on stage st ----
#pragma unroll
        for (int ks = 0; ks < 2; ks++) {
            uint32_t a0, a1, a2, a3;
            ldsm4(a0, a1, a2, a3, addrA_base + so + ks * 32);
#pragma unroll
            for (int p = 0; p < 8; p++) {
                uint32_t b0, b1, b2, b3;
                ldsm4(b0, b1, b2, b3, addrB_base + so + p * 16 * 80 + ks * 32);
                mma_bf16(acc[2 * p],     a0, a1, a2, a3, b0, b1);
                mma_bf16(acc[2 * p + 1], a0, a1, a2, a3, b2, b3);
            }
        }

        if (pf) {
            uint2 p0 = make_uint2(pack_bf16(pa0.x, pa0.y), pack_bf16(pa0.z, pa0.w));
            uint2 p1 = make_uint2(pack_bf16(pa1.x, pa1.y), pack_bf16(pa1.z, pa1.w));
            *(uint2*)((char*)smem + (dstA0 + so_n - sb)) = p0;
            *(uint2*)((char*)smem + (dstA1 + so_n - sb)) = p1;
            CP_WAIT(0);
        }
        __syncthreads();
    }

    // ---- epilogue: +vQp, leaky-relu, dot(Wp), reduce over 256 cols ----
    float pl = 0.0f, ph = 0.0f;  // rows strip*16+(lane>>2) and +8
#pragma unroll
    for (int j = 0; j < 16; j++) {
        const int cb = half * 128 + j * 8 + 2 * (lane & 3);
#pragma unroll
        for (int e = 0; e < 2; e++) {
            const float vq = svqp[cb + e];
            const float wp = swp[cb + e];
            float x = acc[j][e] + vq;
            float h = x > 0.0f ? x : NEG_SLOPE * x;
            pl = fmaf(h, wp, pl);
            x = acc[j][2 + e] + vq;
            h = x > 0.0f ? x : NEG_SLOPE * x;
            ph = fmaf(h, wp, ph);
        }
    }
    pl += __shfl_xor_sync(0xffffffffu, pl, 1);
    pl += __shfl_xor_sync(0xffffffffu, pl, 2);
    ph += __shfl_xor_sync(0xffffffffu, ph, 1);
    ph += __shfl_xor_sync(0xffffffffu, ph, 2);
    if ((lane & 3) == 0) {
        sred[half][strip * 16 + (lane >> 2)]     = pl;
        sred[half][strip * 16 + 8 + (lane >> 2)] = ph;
    }
    __syncthreads();
    if (tid < M_TILE)
        g_scores[(size_t)b * NN + n0 + tid] = sred[0][tid] + sred[1][tid];
}

// ---------------------------------------------------------------------------
// Kernel 3: softmax over N per batch (bp softmax-invariant; ignored)
// ---------------------------------------------------------------------------
__global__ void softmax_kernel() {
    int b = blockIdx.x;
    int tid = threadIdx.x;
    __shared__ float red[512];
    const float* s = g_scores + (size_t)b * NN;
    float mx = -INFINITY;
    for (int i = tid; i < NN; i += 512) mx = fmaxf(mx, s[i]);
    red[tid] = mx;
    __syncthreads();
    for (int o = 256; o > 0; o >>= 1) {
        if (tid < o) red[tid] = fmaxf(red[tid], red[tid + o]);
        __syncthreads();
    }
    float m = red[0];
    __syncthreads();
    float sum = 0.0f;
    for (int i = tid; i < NN; i += 512) {
        float e = __expf(s[i] - m);
        g_pi[(size_t)b * NN + i] = e;
        sum += e;
    }
    red[tid] = sum;
    __syncthreads();
    for (int o = 256; o > 0; o >>= 1) {
        if (tid < o) red[tid] += red[tid + o];
        __syncthreads();
    }
    float inv = 1.0f / red[0];
    for (int i = tid; i < NN; i += 512) g_pi[(size_t)b * NN + i] *= inv;
}

// ---------------------------------------------------------------------------
// Kernel 4: t[b,d] = sum_n pi[b,n] * vI[b,n,d]   (fp32, second vI pass)
// ---------------------------------------------------------------------------
__global__ void attn_kernel(const float* __restrict__ vI) {
    int b = blockIdx.y;
    int n0 = blockIdx.x * 128;
    int d = threadIdx.x;  // 0..511
    __shared__ float sp[128];
    if (d < 128) sp[d] = g_pi[(size_t)b * NN + n0 + d];
    __syncthreads();
    const float* base = vI + ((size_t)b * NN + n0) * DD + d;
    float acc = 0.0f;
#pragma unroll 4
    for (int n = 0; n < 128; n++) acc = fmaf(sp[n], base[(size_t)n * DD], acc);
    atomicAdd(&g_t[b * DD + d], acc);
}

// ---------------------------------------------------------------------------
// Kernel 5: out[b,k] = sum_d t[b,d] * Wi[d,k] + vQp[b,k]  (full-fp32 Wi)
// ---------------------------------------------------------------------------
__global__ void out_kernel(const float* __restrict__ Wi, float* __restrict__ out) {
    int b = blockIdx.x;
    int k = threadIdx.x;
    __shared__ float st[DD];
    st[k]       = g_t[b * DD + k];
    st[k + 256] = g_t[b * DD + 256 + k];
    __syncthreads();
    float acc = g_vQp[b * KK + k];
#pragma unroll 8
    for (int d = 0; d < DD; d++) acc = fmaf(st[d], Wi[d * KK + k], acc);
    out[b * KK + k] = acc;
}

// ---------------------------------------------------------------------------
// Launch. Inputs: vI, vQ, Wi, Wq, bq, Wp, bp
// ---------------------------------------------------------------------------
extern "C" void kernel_launch(void* const* d_in, const int* in_sizes, int n_in,
                              void* d_out, int out_size) {
    const float* vI = (const float*)d_in[0];
    const float* vQ = (const float*)d_in[1];
    const float* Wi = (const float*)d_in[2];
    const float* Wq = (const float*)d_in[3];
    const float* bq = (const float*)d_in[4];
    const float* Wp = (const float*)d_in[5];
    // bp shifts scores uniformly -> softmax-invariant; unused.
    float* out = (float*)d_out;

    cudaFuncSetAttribute(scores_mma_kernel,
                         cudaFuncAttributeMaxDynamicSharedMemorySize, SCORES_SMEM);

    {
        dim3 grid(DD / 32, KK / 32);
        dim3 blk(32, 32);
        transpose_wi_kernel<<<grid, blk>>>(Wi);
    }
    vqp_kernel<<<BB, 256>>>(vQ, Wq, bq);
    {
        dim3 grid(NN / M_TILE, BB);  // 16 x 32 = 512 CTAs
        scores_mma_kernel<<<grid, 512, SCORES_SMEM>>>(vI, Wp);
    }
    softmax_kernel<<<BB, 512>>>();
    {
        dim3 grid(NN / 128, BB);     // 16 x 32 = 512 CTAs
        attn_kernel<<<grid, 512>>>(vI);
    }
    out_kernel<<<BB, 256>>>(Wi, out);
}

// round 8
// speedup vs baseline: 2.9694x; 1.0881x over previous
#include <cuda_runtime.h>
#include <cuda_bf16.h>
#include <math.h>
#include <stdint.h>

// Problem constants
#define BB 32
#define NN 2048
#define DD 512
#define KK 256
#define NEG_SLOPE 0.01f

// Scratch (__device__ globals; no allocation allowed)
__device__ float g_vQp[BB * KK];                 // vQ @ Wq + bq
__device__ float g_t[BB * DD];                   // sum_n exp(s_n) * vI[n,:]
__device__ float g_Z[BB];                        // sum_n exp(s_n)
__device__ __nv_bfloat16 g_WiTbf[KK * DD];       // Wi^T [k][d] in bf16

// ---------------------------------------------------------------------------
// Helpers
// ---------------------------------------------------------------------------
__device__ __forceinline__ uint32_t smem_u32(const void* p) {
    uint32_t a;
    asm("{ .reg .u64 t; cvta.to.shared.u64 t, %1; cvt.u32.u64 %0, t; }"
        : "=r"(a) : "l"(p));
    return a;
}
__device__ __forceinline__ uint32_t pack_bf16(float lo, float hi) {
    uint32_t r;
    asm("cvt.rn.bf16x2.f32 %0, %1, %2;" : "=r"(r) : "f"(hi), "f"(lo));
    return r;
}
__device__ __forceinline__ void cp16(uint32_t smem_addr, const void* gptr) {
    asm volatile("cp.async.cg.shared.global [%0], [%1], 16;"
                 :: "r"(smem_addr), "l"(gptr) : "memory");
}
#define CP_COMMIT() asm volatile("cp.async.commit_group;" ::: "memory")
#define CP_WAIT(n)  asm volatile("cp.async.wait_group %0;" :: "n"(n) : "memory")

__device__ __forceinline__ void ldsm4(uint32_t& r0, uint32_t& r1,
                                      uint32_t& r2, uint32_t& r3, uint32_t addr) {
    asm volatile("ldmatrix.sync.aligned.m8n8.x4.shared.b16 {%0,%1,%2,%3}, [%4];"
                 : "=r"(r0), "=r"(r1), "=r"(r2), "=r"(r3) : "r"(addr));
}
// m16n8k16 bf16 MMA (base-target PTX, sm_80+)
__device__ __forceinline__ void mma_bf16(float* d,
                                         uint32_t a0, uint32_t a1,
                                         uint32_t a2, uint32_t a3,
                                         uint32_t b0, uint32_t b1) {
    asm volatile(
        "mma.sync.aligned.m16n8k16.row.col.f32.bf16.bf16.f32 "
        "{%0,%1,%2,%3}, {%4,%5,%6,%7}, {%8,%9}, {%0,%1,%2,%3};"
        : "+f"(d[0]), "+f"(d[1]), "+f"(d[2]), "+f"(d[3])
        : "r"(a0), "r"(a1), "r"(a2), "r"(a3), "r"(b0), "r"(b1));
}

// ---------------------------------------------------------------------------
// Kernel 0b: WiTbf[k][d] = bf16(Wi[d][k])
// ---------------------------------------------------------------------------
__global__ void transpose_wi_kernel(const float* __restrict__ Wi) {
    __shared__ float t[32][33];
    int d0 = blockIdx.x * 32, k0 = blockIdx.y * 32;
    t[threadIdx.y][threadIdx.x] = Wi[(d0 + threadIdx.y) * KK + (k0 + threadIdx.x)];
    __syncthreads();
    g_WiTbf[(size_t)(k0 + threadIdx.y) * DD + d0 + threadIdx.x] =
        __float2bfloat16_rn(t[threadIdx.x][threadIdx.y]);
}

// ---------------------------------------------------------------------------
// Kernel 1: vQp = vQ @ Wq + bq   (also zeroes g_t, g_Z for this replay)
// ---------------------------------------------------------------------------
__global__ void vqp_kernel(const float* __restrict__ vQ,
                           const float* __restrict__ Wq,
                           const float* __restrict__ bq) {
    int b = blockIdx.x;
    int k = threadIdx.x;
    g_t[b * DD + k] = 0.0f;
    g_t[b * DD + 256 + k] = 0.0f;
    if (k == 0) g_Z[b] = 0.0f;
    __shared__ float sq[DD];
    sq[k]       = vQ[b * DD + k];
    sq[k + 256] = vQ[b * DD + 256 + k];
    __syncthreads();
    float acc = bq[k];
#pragma unroll 8
    for (int d = 0; d < DD; d++) acc = fmaf(sq[d], Wq[d * KK + k], acc);
    g_vQp[b * KK + k] = acc;
}

// ---------------------------------------------------------------------------
// Kernel 2 (dominant, fully fused): scores GEMM (bf16 mma.sync) -> unnormalized
// exp weights -> Z partial + t partial, all in one CTA pass over 128 tokens.
// Scores are O(1)-bounded -> exp() without max-subtraction is fp32-safe, so
// softmax decomposes into CTA-local work + two atomics. The t accumulation
// re-reads the CTA's own vI tile (L2-hot, exact fp32).
// ---------------------------------------------------------------------------
#define M_TILE 128
#define KC 32
#define NCH (DD / KC)               // 16
#define ASTRIDE 40                  // bf16 elems per smem row (80 B)
#define A_BF (M_TILE * ASTRIDE)     // 5120 bf16
#define B_BF (KK * ASTRIDE)         // 10240 bf16
#define STG_BF (A_BF + B_BF)        // 15360 bf16 = 30720 B
#define SCORES_SMEM (2 * STG_BF * 2)  // 61440 bytes

__global__ __launch_bounds__(512, 1)
void scores_mma_kernel(const float* __restrict__ vI,
                       const float* __restrict__ Wp) {
    extern __shared__ __nv_bfloat16 smem[];
    __shared__ float svqp[KK];
    __shared__ float swp[KK];
    __shared__ float sred[2][M_TILE];
    __shared__ float sw[M_TILE];

    const int tid  = threadIdx.x;
    const int lane = tid & 31;
    const int wid  = tid >> 5;
    const int b    = blockIdx.y;
    const int n0   = blockIdx.x * M_TILE;

    if (tid < KK) {
        svqp[tid] = g_vQp[b * KK + tid];
        swp[tid]  = Wp[tid];
    }

    const uint32_t sb = smem_u32(smem);
    const uint32_t stg_bytes = STG_BF * 2;

    // ---- A producer mapping: 1024 float4-quads/chunk, 2 per thread ----
    const int aq0 = tid;
    const int rowA0 = aq0 >> 3, segA0 = aq0 & 7;
    const int aq1 = tid + 512;
    const int rowA1 = aq1 >> 3, segA1 = aq1 & 7;
    const float* srcA0 = vI + ((size_t)b * NN + n0 + rowA0) * DD + segA0 * 4;
    const float* srcA1 = vI + ((size_t)b * NN + n0 + rowA1) * DD + segA1 * 4;
    const uint32_t dstA0 = sb + rowA0 * 80 + segA0 * 8;
    const uint32_t dstA1 = sb + rowA1 * 80 + segA1 * 8;

    // ---- B producer mapping: 1024 16B-quads/chunk, 2 per thread ----
    const int bq0 = tid;
    const int colB0 = bq0 >> 2, kqB0 = bq0 & 3;
    const int bq1 = tid + 512;
    const int colB1 = bq1 >> 2, kqB1 = bq1 & 3;
    const __nv_bfloat16* srcB0 = g_WiTbf + (size_t)colB0 * DD + kqB0 * 8;
    const __nv_bfloat16* srcB1 = g_WiTbf + (size_t)colB1 * DD + kqB1 * 8;
    const uint32_t dstB0 = sb + A_BF * 2 + colB0 * 80 + kqB0 * 16;
    const uint32_t dstB1 = sb + A_BF * 2 + colB1 * 80 + kqB1 * 16;

    // ---- fragment addresses ----
    const int strip = wid >> 1;       // 0..7
    const int half  = wid & 1;        // 0..1
    const uint32_t addrA_base =
        sb + (strip * 16 + (lane & 15)) * 80 + ((lane >> 4) & 1) * 16;
    const uint32_t addrB_base =
        sb + A_BF * 2 +
        (half * 128 + (lane & 7) + ((lane >> 4) & 1) * 8) * 80 +
        ((lane >> 3) & 1) * 16;

    float acc[16][4];
#pragma unroll
    for (int j = 0; j < 16; j++)
#pragma unroll
        for (int e = 0; e < 4; e++) acc[j][e] = 0.0f;

    // ---- prologue: fill stage 0 ----
    {
        float4 v0 = *(const float4*)srcA0;
        float4 v1 = *(const float4*)srcA1;
        uint2 p0 = make_uint2(pack_bf16(v0.x, v0.y), pack_bf16(v0.z, v0.w));
        uint2 p1 = make_uint2(pack_bf16(v1.x, v1.y), pack_bf16(v1.z, v1.w));
        *(uint2*)((char*)smem + (dstA0 - sb)) = p0;
        *(uint2*)((char*)smem + (dstA1 - sb)) = p1;
        cp16(dstB0, srcB0);
        cp16(dstB1, srcB1);
        CP_COMMIT();
        CP_WAIT(0);
    }
    __syncthreads();

    for (int c = 0; c < NCH; c++) {
        const int st = c & 1;
        const uint32_t so = st * stg_bytes;
        const uint32_t so_n = (st ^ 1) * stg_bytes;

        float4 pa0, pa1;
        const bool pf = (c + 1 < NCH);
        if (pf) {
            const int d0 = (c + 1) * KC;
            pa0 = *(const float4*)(srcA0 + d0);
            pa1 = *(const float4*)(srcA1 + d0);
            cp16(dstB0 + so_n, srcB0 + d0);
            cp16(dstB1 + so_n, srcB1 + d0);
            CP_COMMIT();
        }

        // ---- MMA on stage st ----
#pragma unroll
        for (int ks = 0; ks < 2; ks++) {
            uint32_t a0, a1, a2, a3;
            ldsm4(a0, a1, a2, a3, addrA_base + so + ks * 32);
#pragma unroll
            for (int p = 0; p < 8; p++) {
                uint32_t b0, b1, b2, b3;
                ldsm4(b0, b1, b2, b3, addrB_base + so + p * 16 * 80 + ks * 32);
                mma_bf16(acc[2 * p],     a0, a1, a2, a3, b0, b1);
                mma_bf16(acc[2 * p + 1], a0, a1, a2, a3, b2, b3);
            }
        }

        if (pf) {
            uint2 p0 = make_uint2(pack_bf16(pa0.x, pa0.y), pack_bf16(pa0.z, pa0.w));
            uint2 p1 = make_uint2(pack_bf16(pa1.x, pa1.y), pack_bf16(pa1.z, pa1.w));
            *(uint2*)((char*)smem + (dstA0 + so_n - sb)) = p0;
            *(uint2*)((char*)smem + (dstA1 + so_n - sb)) = p1;
            CP_WAIT(0);
        }
        __syncthreads();
    }

    // ---- epilogue 1: +vQp, leaky-relu, dot(Wp), reduce over 256 cols ----
    float pl = 0.0f, ph = 0.0f;
#pragma unroll
    for (int j = 0; j < 16; j++) {
        const int cb = half * 128 + j * 8 + 2 * (lane & 3);
#pragma unroll
        for (int e = 0; e < 2; e++) {
            const float vq = svqp[cb + e];
            const float wp = swp[cb + e];
            float x = acc[j][e] + vq;
            float h = x > 0.0f ? x : NEG_SLOPE * x;
            pl = fmaf(h, wp, pl);
            x = acc[j][2 + e] + vq;
            h = x > 0.0f ? x : NEG_SLOPE * x;
            ph = fmaf(h, wp, ph);
        }
    }
    pl += __shfl_xor_sync(0xffffffffu, pl, 1);
    pl += __shfl_xor_sync(0xffffffffu, pl, 2);
    ph += __shfl_xor_sync(0xffffffffu, ph, 1);
    ph += __shfl_xor_sync(0xffffffffu, ph, 2);
    if ((lane & 3) == 0) {
        sred[half][strip * 16 + (lane >> 2)]     = pl;
        sred[half][strip * 16 + 8 + (lane >> 2)] = ph;
    }
    __syncthreads();

    // ---- epilogue 2: w = exp(score); Z partial ----
    if (tid < M_TILE)
        sw[tid] = __expf(sred[0][tid] + sred[1][tid]);
    __syncthreads();
    if (tid < 32) {
        float z = sw[tid] + sw[tid + 32] + sw[tid + 64] + sw[tid + 96];
        z += __shfl_xor_sync(0xffffffffu, z, 16);
        z += __shfl_xor_sync(0xffffffffu, z, 8);
        z += __shfl_xor_sync(0xffffffffu, z, 4);
        z += __shfl_xor_sync(0xffffffffu, z, 2);
        z += __shfl_xor_sync(0xffffffffu, z, 1);
        if (tid == 0) atomicAdd(&g_Z[b], z);
    }

    // ---- epilogue 3: t[b,d] += sum_n w_n * vI[n0+n, d] (L2-hot fp32 re-read)
    {
        const float* vb = vI + ((size_t)b * NN + n0) * DD + tid;  // d = tid
        float a0 = 0.0f, a1 = 0.0f;
#pragma unroll 4
        for (int n = 0; n < M_TILE; n += 2) {
            a0 = fmaf(sw[n],     vb[(size_t)n * DD],       a0);
            a1 = fmaf(sw[n + 1], vb[(size_t)(n + 1) * DD], a1);
        }
        atomicAdd(&g_t[b * DD + tid], a0 + a1);
    }
}

// ---------------------------------------------------------------------------
// Kernel 3: out[b,k] = (t[b,:]/Z[b]) @ Wi[:,k] + vQp[b,k]   (full-fp32 Wi)
// ---------------------------------------------------------------------------
__global__ void out_kernel(const float* __restrict__ Wi, float* __restrict__ out) {
    int b = blockIdx.x;
    int k = threadIdx.x;
    __shared__ float st[DD];
    const float invZ = 1.0f / g_Z[b];
    st[k]       = g_t[b * DD + k] * invZ;
    st[k + 256] = g_t[b * DD + 256 + k] * invZ;
    __syncthreads();
    float acc = g_vQp[b * KK + k];
#pragma unroll 8
    for (int d = 0; d < DD; d++) acc = fmaf(st[d], Wi[d * KK + k], acc);
    out[b * KK + k] = acc;
}

// ---------------------------------------------------------------------------
// Launch. Inputs: vI, vQ, Wi, Wq, bq, Wp, bp
// ---------------------------------------------------------------------------
extern "C" void kernel_launch(void* const* d_in, const int* in_sizes, int n_in,
                              void* d_out, int out_size) {
    const float* vI = (const float*)d_in[0];
    const float* vQ = (const float*)d_in[1];
    const float* Wi = (const float*)d_in[2];
    const float* Wq = (const float*)d_in[3];
    const float* bq = (const float*)d_in[4];
    const float* Wp = (const float*)d_in[5];
    // bp shifts scores uniformly -> softmax-invariant; unused.
    float* out = (float*)d_out;

    cudaFuncSetAttribute(scores_mma_kernel,
                         cudaFuncAttributeMaxDynamicSharedMemorySize, SCORES_SMEM);

    {
        dim3 grid(DD / 32, KK / 32);
        dim3 blk(32, 32);
        transpose_wi_kernel<<<grid, blk>>>(Wi);
    }
    vqp_kernel<<<BB, 256>>>(vQ, Wq, bq);
    {
        dim3 grid(NN / M_TILE, BB);  // 16 x 32 = 512 CTAs
        scores_mma_kernel<<<grid, 512, SCORES_SMEM>>>(vI, Wp);
    }
    out_kernel<<<BB, 256>>>(Wi, out);
}

// round 10
// speedup vs baseline: 4.1088x; 1.3837x over previous
#include <cuda_runtime.h>
#include <cuda_bf16.h>
#include <math.h>
#include <stdint.h>

// Problem constants
#define BB 32
#define NN 2048
#define DD 512
#define KK 256
#define NEG_SLOPE 0.01f

// Scratch (__device__ globals; no allocation allowed)
__device__ float g_vQp[BB * KK];                 // vQ @ Wq + bq
__device__ float g_t[BB * DD];                   // sum_n exp(s_n) * vI[n,:]
__device__ float g_Z[BB];                        // sum_n exp(s_n)
__device__ __nv_bfloat16 g_WiTbf[KK * DD];       // Wi^T [k][d] in bf16

// ---------------------------------------------------------------------------
// Helpers
// ---------------------------------------------------------------------------
__device__ __forceinline__ uint32_t smem_u32(const void* p) {
    uint32_t a;
    asm("{ .reg .u64 t; cvta.to.shared.u64 t, %1; cvt.u32.u64 %0, t; }"
        : "=r"(a) : "l"(p));
    return a;
}
__device__ __forceinline__ uint32_t pack_bf16(float lo, float hi) {
    uint32_t r;
    asm("cvt.rn.bf16x2.f32 %0, %1, %2;" : "=r"(r) : "f"(hi), "f"(lo));
    return r;
}
__device__ __forceinline__ void cp16(uint32_t smem_addr, const void* gptr) {
    asm volatile("cp.async.cg.shared.global [%0], [%1], 16;"
                 :: "r"(smem_addr), "l"(gptr) : "memory");
}
#define CP_COMMIT() asm volatile("cp.async.commit_group;" ::: "memory")
#define CP_WAIT(n)  asm volatile("cp.async.wait_group %0;" :: "n"(n) : "memory")

__device__ __forceinline__ void ldsm4(uint32_t& r0, uint32_t& r1,
                                      uint32_t& r2, uint32_t& r3, uint32_t addr) {
    asm volatile("ldmatrix.sync.aligned.m8n8.x4.shared.b16 {%0,%1,%2,%3}, [%4];"
                 : "=r"(r0), "=r"(r1), "=r"(r2), "=r"(r3) : "r"(addr));
}
// m16n8k16 bf16 MMA (base-target PTX, sm_80+)
__device__ __forceinline__ void mma_bf16(float* d,
                                         uint32_t a0, uint32_t a1,
                                         uint32_t a2, uint32_t a3,
                                         uint32_t b0, uint32_t b1) {
    asm volatile(
        "mma.sync.aligned.m16n8k16.row.col.f32.bf16.bf16.f32 "
        "{%0,%1,%2,%3}, {%4,%5,%6,%7}, {%8,%9}, {%0,%1,%2,%3};"
        : "+f"(d[0]), "+f"(d[1]), "+f"(d[2]), "+f"(d[3])
        : "r"(a0), "r"(a1), "r"(a2), "r"(a3), "r"(b0), "r"(b1));
}

// ---------------------------------------------------------------------------
// Kernel 0b: WiTbf[k][d] = bf16(Wi[d][k])
// ---------------------------------------------------------------------------
__global__ void transpose_wi_kernel(const float* __restrict__ Wi) {
    __shared__ float t[32][33];
    int d0 = blockIdx.x * 32, k0 = blockIdx.y * 32;
    t[threadIdx.y][threadIdx.x] = Wi[(d0 + threadIdx.y) * KK + (k0 + threadIdx.x)];
    __syncthreads();
    g_WiTbf[(size_t)(k0 + threadIdx.y) * DD + d0 + threadIdx.x] =
        __float2bfloat16_rn(t[threadIdx.x][threadIdx.y]);
}

// ---------------------------------------------------------------------------
// Kernel 1: vQp = vQ @ Wq + bq  (split-d: grid (B,4), 64 k x 4 d-groups)
// blockIdx.y==0 slice also zeroes g_t, g_Z for this replay.
// ---------------------------------------------------------------------------
__global__ __launch_bounds__(256)
void vqp_kernel(const float* __restrict__ vQ,
                const float* __restrict__ Wq,
                const float* __restrict__ bq) {
    const int b  = blockIdx.x;
    const int k0 = blockIdx.y * 64;
    const int tid = threadIdx.x;
    const int kl = tid & 63;
    const int dg = tid >> 6;

    __shared__ float sq[DD];
    __shared__ float sred[4][64];

    sq[tid]       = vQ[b * DD + tid];
    sq[tid + 256] = vQ[b * DD + 256 + tid];
    if (blockIdx.y == 0) {
        g_t[b * DD + tid] = 0.0f;
        g_t[b * DD + 256 + tid] = 0.0f;
        if (tid == 0) g_Z[b] = 0.0f;
    }
    __syncthreads();

    const float* w = Wq + k0 + kl;
    const int d0 = dg * 128;
    float a0 = 0.0f, a1 = 0.0f, a2 = 0.0f, a3 = 0.0f;
#pragma unroll 8
    for (int d = d0; d < d0 + 128; d += 4) {
        a0 = fmaf(sq[d],     w[(size_t)d * KK],       a0);
        a1 = fmaf(sq[d + 1], w[(size_t)(d + 1) * KK], a1);
        a2 = fmaf(sq[d + 2], w[(size_t)(d + 2) * KK], a2);
        a3 = fmaf(sq[d + 3], w[(size_t)(d + 3) * KK], a3);
    }
    sred[dg][kl] = (a0 + a1) + (a2 + a3);
    __syncthreads();
    if (tid < 64)
        g_vQp[b * KK + k0 + tid] = bq[k0 + tid] +
            ((sred[0][tid] + sred[1][tid]) + (sred[2][tid] + sred[3][tid]));
}

// ---------------------------------------------------------------------------
// Kernel 2 (dominant, fully fused): scores GEMM (bf16 mma.sync) -> unnormalized
// exp weights -> Z partial + t partial, one CTA pass over 128 tokens.
// ---------------------------------------------------------------------------
#define M_TILE 128
#define KC 32
#define NCH (DD / KC)               // 16
#define ASTRIDE 40                  // bf16 elems per smem row (80 B)
#define A_BF (M_TILE * ASTRIDE)     // 5120 bf16
#define B_BF (KK * ASTRIDE)         // 10240 bf16
#define STG_BF (A_BF + B_BF)        // 15360 bf16 = 30720 B
#define SCORES_SMEM (2 * STG_BF * 2)  // 61440 bytes

__global__ __launch_bounds__(512, 1)
void scores_mma_kernel(const float* __restrict__ vI,
                       const float* __restrict__ Wp) {
    extern __shared__ __nv_bfloat16 smem[];
    __shared__ float svqp[KK];
    __shared__ float swp[KK];
    __shared__ float sred[2][M_TILE];
    __shared__ float sw[M_TILE];

    const int tid  = threadIdx.x;
    const int lane = tid & 31;
    const int wid  = tid >> 5;
    const int b    = blockIdx.y;
    const int n0   = blockIdx.x * M_TILE;

    if (tid < KK) {
        svqp[tid] = g_vQp[b * KK + tid];
        swp[tid]  = Wp[tid];
    }

    const uint32_t sb = smem_u32(smem);
    const uint32_t stg_bytes = STG_BF * 2;

    // ---- A producer mapping: 1024 float4-quads/chunk, 2 per thread ----
    const int aq0 = tid;
    const int rowA0 = aq0 >> 3, segA0 = aq0 & 7;
    const int aq1 = tid + 512;
    const int rowA1 = aq1 >> 3, segA1 = aq1 & 7;
    const float* srcA0 = vI + ((size_t)b * NN + n0 + rowA0) * DD + segA0 * 4;
    const float* srcA1 = vI + ((size_t)b * NN + n0 + rowA1) * DD + segA1 * 4;
    const uint32_t dstA0 = sb + rowA0 * 80 + segA0 * 8;
    const uint32_t dstA1 = sb + rowA1 * 80 + segA1 * 8;

    // ---- B producer mapping: 1024 16B-quads/chunk, 2 per thread ----
    const int bq0 = tid;
    const int colB0 = bq0 >> 2, kqB0 = bq0 & 3;
    const int bq1 = tid + 512;
    const int colB1 = bq1 >> 2, kqB1 = bq1 & 3;
    const __nv_bfloat16* srcB0 = g_WiTbf + (size_t)colB0 * DD + kqB0 * 8;
    const __nv_bfloat16* srcB1 = g_WiTbf + (size_t)colB1 * DD + kqB1 * 8;
    const uint32_t dstB0 = sb + A_BF * 2 + colB0 * 80 + kqB0 * 16;
    const uint32_t dstB1 = sb + A_BF * 2 + colB1 * 80 + kqB1 * 16;

    // ---- fragment addresses ----
    const int strip = wid >> 1;       // 0..7
    const int half  = wid & 1;        // 0..1
    const uint32_t addrA_base =
        sb + (strip * 16 + (lane & 15)) * 80 + ((lane >> 4) & 1) * 16;
    const uint32_t addrB_base =
        sb + A_BF * 2 +
        (half * 128 + (lane & 7) + ((lane >> 4) & 1) * 8) * 80 +
        ((lane >> 3) & 1) * 16;

    float acc[16][4];
#pragma unroll
    for (int j = 0; j < 16; j++)
#pragma unroll
        for (int e = 0; e < 4; e++) acc[j][e] = 0.0f;

    // ---- prologue: fill stage 0 ----
    {
        float4 v0 = *(const float4*)srcA0;
        float4 v1 = *(const float4*)srcA1;
        uint2 p0 = make_uint2(pack_bf16(v0.x, v0.y), pack_bf16(v0.z, v0.w));
        uint2 p1 = make_uint2(pack_bf16(v1.x, v1.y), pack_bf16(v1.z, v1.w));
        *(uint2*)((char*)smem + (dstA0 - sb)) = p0;
        *(uint2*)((char*)smem + (dstA1 - sb)) = p1;
        cp16(dstB0, srcB0);
        cp16(dstB1, srcB1);
        CP_COMMIT();
        CP_WAIT(0);
    }
    __syncthreads();

    for (int c = 0; c < NCH; c++) {
        const int st = c & 1;
        const uint32_t so = st * stg_bytes;
        const uint32_t so_n = (st ^ 1) * stg_bytes;

        float4 pa0, pa1;
        const bool pf = (c + 1 < NCH);
        if (pf) {
            const int d0 = (c + 1) * KC;
            pa0 = *(const float4*)(srcA0 + d0);
            pa1 = *(const float4*)(srcA1 + d0);
            cp16(dstB0 + so_n, srcB0 + d0);
            cp16(dstB1 + so_n, srcB1 + d0);
            CP_COMMIT();
        }

        // ---- MMA on stage st ----
#pragma unroll
        for (int ks = 0; ks < 2; ks++) {
            uint32_t a0, a1, a2, a3;
            ldsm4(a0, a1, a2, a3, addrA_base + so + ks * 32);
#pragma unroll
            for (int p = 0; p < 8; p++) {
                uint32_t b0, b1, b2, b3;
                ldsm4(b0, b1, b2, b3, addrB_base + so + p * 16 * 80 + ks * 32);
                mma_bf16(acc[2 * p],     a0, a1, a2, a3, b0, b1);
                mma_bf16(acc[2 * p + 1], a0, a1, a2, a3, b2, b3);
            }
        }

        if (pf) {
            uint2 p0 = make_uint2(pack_bf16(pa0.x, pa0.y), pack_bf16(pa0.z, pa0.w));
            uint2 p1 = make_uint2(pack_bf16(pa1.x, pa1.y), pack_bf16(pa1.z, pa1.w));
            *(uint2*)((char*)smem + (dstA0 + so_n - sb)) = p0;
            *(uint2*)((char*)smem + (dstA1 + so_n - sb)) = p1;
            CP_WAIT(0);
        }
        __syncthreads();
    }

    // ---- epilogue 1: +vQp, leaky-relu, dot(Wp), reduce over 256 cols ----
    float pl = 0.0f, ph = 0.0f;
#pragma unroll
    for (int j = 0; j < 16; j++) {
        const int cb = half * 128 + j * 8 + 2 * (lane & 3);
#pragma unroll
        for (int e = 0; e < 2; e++) {
            const float vq = svqp[cb + e];
            const float wp = swp[cb + e];
            float x = acc[j][e] + vq;
            float h = x > 0.0f ? x : NEG_SLOPE * x;
            pl = fmaf(h, wp, pl);
            x = acc[j][2 + e] + vq;
            h = x > 0.0f ? x : NEG_SLOPE * x;
            ph = fmaf(h, wp, ph);
        }
    }
    pl += __shfl_xor_sync(0xffffffffu, pl, 1);
    pl += __shfl_xor_sync(0xffffffffu, pl, 2);
    ph += __shfl_xor_sync(0xffffffffu, ph, 1);
    ph += __shfl_xor_sync(0xffffffffu, ph, 2);
    if ((lane & 3) == 0) {
        sred[half][strip * 16 + (lane >> 2)]     = pl;
        sred[half][strip * 16 + 8 + (lane >> 2)] = ph;
    }
    __syncthreads();

    // ---- epilogue 2: w = exp(score); Z partial ----
    if (tid < M_TILE)
        sw[tid] = __expf(sred[0][tid] + sred[1][tid]);
    __syncthreads();
    if (tid < 32) {
        float z = sw[tid] + sw[tid + 32] + sw[tid + 64] + sw[tid + 96];
        z += __shfl_xor_sync(0xffffffffu, z, 16);
        z += __shfl_xor_sync(0xffffffffu, z, 8);
        z += __shfl_xor_sync(0xffffffffu, z, 4);
        z += __shfl_xor_sync(0xffffffffu, z, 2);
        z += __shfl_xor_sync(0xffffffffu, z, 1);
        if (tid == 0) atomicAdd(&g_Z[b], z);
    }

    // ---- epilogue 3: t[b,d] += sum_n w_n * vI[n0+n, d] (L2-hot fp32 re-read)
    {
        const float* vb = vI + ((size_t)b * NN + n0) * DD + tid;  // d = tid
        float a0 = 0.0f, a1 = 0.0f;
#pragma unroll 4
        for (int n = 0; n < M_TILE; n += 2) {
            a0 = fmaf(sw[n],     vb[(size_t)n * DD],       a0);
            a1 = fmaf(sw[n + 1], vb[(size_t)(n + 1) * DD], a1);
        }
        atomicAdd(&g_t[b * DD + tid], a0 + a1);
    }
}

// ---------------------------------------------------------------------------
// Kernel 3: out[b,k] = (t[b,:]/Z[b]) @ Wi[:,k] + vQp[b,k]
// split-d: grid (B,4), 64 k x 4 d-groups of 128, smem reduce.
// ---------------------------------------------------------------------------
__global__ __launch_bounds__(256)
void out_kernel(const float* __restrict__ Wi, float* __restrict__ out) {
    const int b  = blockIdx.x;
    const int k0 = blockIdx.y * 64;
    const int tid = threadIdx.x;
    const int kl = tid & 63;
    const int dg = tid >> 6;

    __shared__ float st[DD];
    __shared__ float sred[4][64];

    const float invZ = 1.0f / g_Z[b];
    st[tid]       = g_t[b * DD + tid] * invZ;
    st[tid + 256] = g_t[b * DD + 256 + tid] * invZ;
    __syncthreads();

    const float* w = Wi + k0 + kl;
    const int d0 = dg * 128;
    float a0 = 0.0f, a1 = 0.0f, a2 = 0.0f, a3 = 0.0f;
#pragma unroll 8
    for (int d = d0; d < d0 + 128; d += 4) {
        a0 = fmaf(st[d],     w[(size_t)d * KK],       a0);
        a1 = fmaf(st[d + 1], w[(size_t)(d + 1) * KK], a1);
        a2 = fmaf(st[d + 2], w[(size_t)(d + 2) * KK], a2);
        a3 = fmaf(st[d + 3], w[(size_t)(d + 3) * KK], a3);
    }
    sred[dg][kl] = (a0 + a1) + (a2 + a3);
    __syncthreads();
    if (tid < 64)
        out[b * KK + k0 + tid] = g_vQp[b * KK + k0 + tid] +
            ((sred[0][tid] + sred[1][tid]) + (sred[2][tid] + sred[3][tid]));
}

// ---------------------------------------------------------------------------
// Launch. Inputs: vI, vQ, Wi, Wq, bq, Wp, bp
// ---------------------------------------------------------------------------
extern "C" void kernel_launch(void* const* d_in, const int* in_sizes, int n_in,
                              void* d_out, int out_size) {
    const float* vI = (const float*)d_in[0];
    const float* vQ = (const float*)d_in[1];
    const float* Wi = (const float*)d_in[2];
    const float* Wq = (const float*)d_in[3];
    const float* bq = (const float*)d_in[4];
    const float* Wp = (const float*)d_in[5];
    // bp shifts scores uniformly -> softmax-invariant; unused.
    float* out = (float*)d_out;

    cudaFuncSetAttribute(scores_mma_kernel,
                         cudaFuncAttributeMaxDynamicSharedMemorySize, SCORES_SMEM);

    {
        dim3 grid(DD / 32, KK / 32);
        dim3 blk(32, 32);
        transpose_wi_kernel<<<grid, blk>>>(Wi);
    }
    {
        dim3 grid(BB, 4);
        vqp_kernel<<<grid, 256>>>(vQ, Wq, bq);
    }
    {
        dim3 grid(NN / M_TILE, BB);  // 16 x 32 = 512 CTAs
        scores_mma_kernel<<<grid, 512, SCORES_SMEM>>>(vI, Wp);
    }
    {
        dim3 grid(BB, 4);
        out_kernel<<<grid, 256>>>(Wi, out);
    }
}

// round 11
// speedup vs baseline: 5.1899x; 1.2631x over previous
#include <cuda_runtime.h>
#include <cuda_bf16.h>
#include <math.h>
#include <stdint.h>

// Problem constants
#define BB 32
#define NN 2048
#define DD 512
#define KK 256
#define NEG_SLOPE 0.01f

// Scratch (__device__ globals; no allocation allowed)
__device__ float g_vQp[BB * KK];                 // vQ @ Wq + bq
__device__ float g_t[BB * DD];                   // sum_n exp(s_n) * vI[n,:]
__device__ float g_Z[BB];                        // sum_n exp(s_n)
__device__ __nv_bfloat16 g_WiTbf[KK * DD];       // Wi^T [k][d] in bf16

// ---------------------------------------------------------------------------
// Helpers
// ---------------------------------------------------------------------------
__device__ __forceinline__ uint32_t smem_u32(const void* p) {
    uint32_t a;
    asm("{ .reg .u64 t; cvta.to.shared.u64 t, %1; cvt.u32.u64 %0, t; }"
        : "=r"(a) : "l"(p));
    return a;
}
__device__ __forceinline__ uint32_t pack_bf16(float lo, float hi) {
    uint32_t r;
    asm("cvt.rn.bf16x2.f32 %0, %1, %2;" : "=r"(r) : "f"(hi), "f"(lo));
    return r;
}
__device__ __forceinline__ void cp16(uint32_t smem_addr, const void* gptr) {
    asm volatile("cp.async.cg.shared.global [%0], [%1], 16;"
                 :: "r"(smem_addr), "l"(gptr) : "memory");
}
#define CP_COMMIT() asm volatile("cp.async.commit_group;" ::: "memory")
#define CP_WAIT(n)  asm volatile("cp.async.wait_group %0;" :: "n"(n) : "memory")

__device__ __forceinline__ void ldsm4(uint32_t& r0, uint32_t& r1,
                                      uint32_t& r2, uint32_t& r3, uint32_t addr) {
    asm volatile("ldmatrix.sync.aligned.m8n8.x4.shared.b16 {%0,%1,%2,%3}, [%4];"
                 : "=r"(r0), "=r"(r1), "=r"(r2), "=r"(r3) : "r"(addr));
}
// m16n8k16 bf16 MMA (base-target PTX, sm_80+)
__device__ __forceinline__ void mma_bf16(float* d,
                                         uint32_t a0, uint32_t a1,
                                         uint32_t a2, uint32_t a3,
                                         uint32_t b0, uint32_t b1) {
    asm volatile(
        "mma.sync.aligned.m16n8k16.row.col.f32.bf16.bf16.f32 "
        "{%0,%1,%2,%3}, {%4,%5,%6,%7}, {%8,%9}, {%0,%1,%2,%3};"
        : "+f"(d[0]), "+f"(d[1]), "+f"(d[2]), "+f"(d[3])
        : "r"(a0), "r"(a1), "r"(a2), "r"(a3), "r"(b0), "r"(b1));
}

// ---------------------------------------------------------------------------
// Kernel 0b: WiTbf[k][d] = bf16(Wi[d][k])
// ---------------------------------------------------------------------------
__global__ void transpose_wi_kernel(const float* __restrict__ Wi) {
    __shared__ float t[32][33];
    int d0 = blockIdx.x * 32, k0 = blockIdx.y * 32;
    t[threadIdx.y][threadIdx.x] = Wi[(d0 + threadIdx.y) * KK + (k0 + threadIdx.x)];
    __syncthreads();
    g_WiTbf[(size_t)(k0 + threadIdx.y) * DD + d0 + threadIdx.x] =
        __float2bfloat16_rn(t[threadIdx.x][threadIdx.y]);
}

// ---------------------------------------------------------------------------
// Kernel 1: vQp = vQ @ Wq + bq  (split-d: grid (B,8), 32 k x 8 d-groups of 64)
// blockIdx.y==0 slice also zeroes g_t, g_Z for this replay.
// ---------------------------------------------------------------------------
__global__ __launch_bounds__(256)
void vqp_kernel(const float* __restrict__ vQ,
                const float* __restrict__ Wq,
                const float* __restrict__ bq) {
    const int b  = blockIdx.x;
    const int k0 = blockIdx.y * 32;
    const int tid = threadIdx.x;
    const int kl = tid & 31;
    const int dg = tid >> 5;

    __shared__ float sq[DD];
    __shared__ float sred[8][32];

    sq[tid]       = vQ[b * DD + tid];
    sq[tid + 256] = vQ[b * DD + 256 + tid];
    if (blockIdx.y == 0) {
        g_t[b * DD + tid] = 0.0f;
        g_t[b * DD + 256 + tid] = 0.0f;
        if (tid == 0) g_Z[b] = 0.0f;
    }
    __syncthreads();

    const float* w = Wq + k0 + kl;
    const int d0 = dg * 64;
    float a0 = 0.0f, a1 = 0.0f, a2 = 0.0f, a3 = 0.0f;
#pragma unroll 8
    for (int d = d0; d < d0 + 64; d += 4) {
        a0 = fmaf(sq[d],     w[(size_t)d * KK],       a0);
        a1 = fmaf(sq[d + 1], w[(size_t)(d + 1) * KK], a1);
        a2 = fmaf(sq[d + 2], w[(size_t)(d + 2) * KK], a2);
        a3 = fmaf(sq[d + 3], w[(size_t)(d + 3) * KK], a3);
    }
    sred[dg][kl] = (a0 + a1) + (a2 + a3);
    __syncthreads();
    if (tid < 32) {
        float s = 0.0f;
#pragma unroll
        for (int g = 0; g < 8; g++) s += sred[g][tid];
        g_vQp[b * KK + k0 + tid] = bq[k0 + tid] + s;
    }
}

// ---------------------------------------------------------------------------
// Kernel 2 (dominant, fully fused): scores GEMM (bf16 mma.sync, 4x4 warp map,
// KC=64) -> unnormalized exp -> Z partial + t partial in one CTA pass.
// Warp w: row strip (w&3)*32, col quarter (w>>2)*64.
// Smem rows 72 bf16 (144 B): 9r mod 8 = r mod 8 -> ldsm conflict-free.
// ---------------------------------------------------------------------------
#define M_TILE 128
#define KC 64
#define NCH (DD / KC)               // 8
#define AROW 144                    // bytes per smem row (64 bf16 + 8 pad)
#define A_BYTES (M_TILE * AROW)     // 18432
#define B_BYTES (KK * AROW)         // 36864
#define STG_BYTES (A_BYTES + B_BYTES)   // 55296
#define SCORES_SMEM (2 * STG_BYTES)     // 110592

__global__ __launch_bounds__(512, 1)
void scores_mma_kernel(const float* __restrict__ vI,
                       const float* __restrict__ Wp) {
    extern __shared__ char smem[];
    __shared__ float svqp[KK];
    __shared__ float swp[KK];
    __shared__ float sred[4][M_TILE];
    __shared__ float sw[M_TILE];

    const int tid  = threadIdx.x;
    const int lane = tid & 31;
    const int wid  = tid >> 5;
    const int b    = blockIdx.y;
    const int n0   = blockIdx.x * M_TILE;

    if (tid < KK) {
        svqp[tid] = g_vQp[b * KK + tid];
        swp[tid]  = Wp[tid];
    }

    const uint32_t sb = smem_u32(smem);

    // ---- A producer: 2048 float4-quads/chunk, 4 per thread ----
    // quad qi = tid + 512*i: row = qi>>4 (16 quads/row), seg = qi&15
    const float* srcA[4];
    uint32_t offA[4];
#pragma unroll
    for (int i = 0; i < 4; i++) {
        const int qi = tid + 512 * i;
        const int row = qi >> 4, seg = qi & 15;
        srcA[i] = vI + ((size_t)b * NN + n0 + row) * DD + seg * 4;
        offA[i] = row * AROW + seg * 8;
    }
    // ---- B producer: 2048 16B-quads/chunk, 4 per thread ----
    // quad qi: row = qi>>3 (8 quads/row of 128B), kq = qi&7
    const __nv_bfloat16* srcB[4];
    uint32_t dstB[4];
#pragma unroll
    for (int i = 0; i < 4; i++) {
        const int qi = tid + 512 * i;
        const int row = qi >> 3, kq = qi & 7;
        srcB[i] = g_WiTbf + (size_t)row * DD + kq * 8;
        dstB[i] = sb + A_BYTES + row * AROW + kq * 16;
    }

    // ---- fragment base addresses (warp: strip s rows, quarter q cols) ----
    const int s = wid & 3;            // 0..3 -> rows s*32..+31
    const int q = wid >> 2;           // 0..3 -> cols q*64..+63
    const uint32_t addrA_base =
        sb + (s * 32 + (lane & 15)) * AROW + ((lane >> 4) & 1) * 16;
    const uint32_t addrB_base =
        sb + A_BYTES +
        (q * 64 + (lane & 7) + ((lane >> 4) & 1) * 8) * AROW +
        ((lane >> 3) & 1) * 16;

    float acc[16][4];   // [mt*8 + j2][e], mt in 0..1 (16-row tiles), j2 = 8-col tile
#pragma unroll
    for (int j = 0; j < 16; j++)
#pragma unroll
        for (int e = 0; e < 4; e++) acc[j][e] = 0.0f;

    // ---- prologue: fill stage 0 ----
#pragma unroll
    for (int i = 0; i < 4; i++) {
        float4 v = *(const float4*)srcA[i];
        uint2 p = make_uint2(pack_bf16(v.x, v.y), pack_bf16(v.z, v.w));
        *(uint2*)(smem + offA[i]) = p;
        cp16(dstB[i], srcB[i]);
    }
    CP_COMMIT();
    CP_WAIT(0);
    __syncthreads();

    for (int c = 0; c < NCH; c++) {
        const int st = c & 1;
        const uint32_t so = st * STG_BYTES;
        const uint32_t so_n = (st ^ 1) * STG_BYTES;

        float4 pa[4];
        const bool pf = (c + 1 < NCH);
        if (pf) {
            const int d0 = (c + 1) * KC;
#pragma unroll
            for (int i = 0; i < 4; i++) {
                pa[i] = *(const float4*)(srcA[i] + d0);
                cp16(dstB[i] + (so_n - 0), srcB[i] + d0);
            }
            CP_COMMIT();
        }

        // ---- MMA on stage st: 4 ksteps x (2 A-ldsm + 4 B-ldsm + 16 MMA) ----
#pragma unroll
        for (int ks = 0; ks < 4; ks++) {
            uint32_t a[2][4];
#pragma unroll
            for (int mt = 0; mt < 2; mt++)
                ldsm4(a[mt][0], a[mt][1], a[mt][2], a[mt][3],
                      addrA_base + so + mt * 16 * AROW + ks * 32);
#pragma unroll
            for (int pt = 0; pt < 4; pt++) {
                uint32_t b0, b1, b2, b3;
                ldsm4(b0, b1, b2, b3,
                      addrB_base + so + pt * 16 * AROW + ks * 32);
#pragma unroll
                for (int mt = 0; mt < 2; mt++) {
                    mma_bf16(acc[mt * 8 + pt * 2],
                             a[mt][0], a[mt][1], a[mt][2], a[mt][3], b0, b1);
                    mma_bf16(acc[mt * 8 + pt * 2 + 1],
                             a[mt][0], a[mt][1], a[mt][2], a[mt][3], b2, b3);
                }
            }
        }

        if (pf) {
#pragma unroll
            for (int i = 0; i < 4; i++) {
                uint2 p = make_uint2(pack_bf16(pa[i].x, pa[i].y),
                                     pack_bf16(pa[i].z, pa[i].w));
                *(uint2*)(smem + so_n + offA[i]) = p;
            }
            CP_WAIT(0);
        }
        __syncthreads();
    }

    // ---- epilogue 1: +vQp, leaky-relu, dot(Wp); per-quarter row partials ----
    float p00 = 0.0f, p01 = 0.0f, p10 = 0.0f, p11 = 0.0f;  // [mt][h]
#pragma unroll
    for (int mt = 0; mt < 2; mt++) {
#pragma unroll
        for (int j2 = 0; j2 < 8; j2++) {
            const int cb = q * 64 + j2 * 8 + 2 * (lane & 3);
            const float* ac = acc[mt * 8 + j2];
#pragma unroll
            for (int e = 0; e < 2; e++) {
                const float vq = svqp[cb + e];
                const float wp = swp[cb + e];
                float x = ac[e] + vq;
                float h = x > 0.0f ? x : NEG_SLOPE * x;
                float x2 = ac[2 + e] + vq;
                float h2 = x2 > 0.0f ? x2 : NEG_SLOPE * x2;
                if (mt == 0) { p00 = fmaf(h, wp, p00); p01 = fmaf(h2, wp, p01); }
                else         { p10 = fmaf(h, wp, p10); p11 = fmaf(h2, wp, p11); }
            }
        }
    }
    p00 += __shfl_xor_sync(0xffffffffu, p00, 1);
    p00 += __shfl_xor_sync(0xffffffffu, p00, 2);
    p01 += __shfl_xor_sync(0xffffffffu, p01, 1);
    p01 += __shfl_xor_sync(0xffffffffu, p01, 2);
    p10 += __shfl_xor_sync(0xffffffffu, p10, 1);
    p10 += __shfl_xor_sync(0xffffffffu, p10, 2);
    p11 += __shfl_xor_sync(0xffffffffu, p11, 1);
    p11 += __shfl_xor_sync(0xffffffffu, p11, 2);
    if ((lane & 3) == 0) {
        const int r = s * 32 + (lane >> 2);
        sred[q][r]      = p00;
        sred[q][r + 8]  = p01;
        sred[q][r + 16] = p10;
        sred[q][r + 24] = p11;
    }
    __syncthreads();

    // ---- epilogue 2: w = exp(score); Z partial ----
    if (tid < M_TILE)
        sw[tid] = __expf((sred[0][tid] + sred[1][tid]) +
                         (sred[2][tid] + sred[3][tid]));
    __syncthreads();
    if (tid < 32) {
        float z = (sw[tid] + sw[tid + 32]) + (sw[tid + 64] + sw[tid + 96]);
        z += __shfl_xor_sync(0xffffffffu, z, 16);
        z += __shfl_xor_sync(0xffffffffu, z, 8);
        z += __shfl_xor_sync(0xffffffffu, z, 4);
        z += __shfl_xor_sync(0xffffffffu, z, 2);
        z += __shfl_xor_sync(0xffffffffu, z, 1);
        if (tid == 0) atomicAdd(&g_Z[b], z);
    }

    // ---- epilogue 3: t[b,d] += sum_n w_n * vI[n0+n, d] (L2-hot fp32 re-read)
    {
        const float* vb = vI + ((size_t)b * NN + n0) * DD + tid;  // d = tid
        float a0 = 0.0f, a1 = 0.0f, a2 = 0.0f, a3 = 0.0f;
#pragma unroll 8
        for (int n = 0; n < M_TILE; n += 4) {
            a0 = fmaf(sw[n],     vb[(size_t)n * DD],       a0);
            a1 = fmaf(sw[n + 1], vb[(size_t)(n + 1) * DD], a1);
            a2 = fmaf(sw[n + 2], vb[(size_t)(n + 2) * DD], a2);
            a3 = fmaf(sw[n + 3], vb[(size_t)(n + 3) * DD], a3);
        }
        atomicAdd(&g_t[b * DD + tid], (a0 + a1) + (a2 + a3));
    }
}

// ---------------------------------------------------------------------------
// Kernel 3: out[b,k] = (t[b,:]/Z[b]) @ Wi[:,k] + vQp[b,k]
// split-d: grid (B,8), 32 k-cols x 8 d-groups of 64.
// ---------------------------------------------------------------------------
__global__ __launch_bounds__(256)
void out_kernel(const float* __restrict__ Wi, float* __restrict__ out) {
    const int b  = blockIdx.x;
    const int k0 = blockIdx.y * 32;
    const int tid = threadIdx.x;
    const int kl = tid & 31;
    const int dg = tid >> 5;

    __shared__ float st[DD];
    __shared__ float sred[8][32];

    const float invZ = 1.0f / g_Z[b];
    st[tid]       = g_t[b * DD + tid] * invZ;
    st[tid + 256] = g_t[b * DD + 256 + tid] * invZ;
    __syncthreads();

    const float* w = Wi + k0 + kl;
    const int d0 = dg * 64;
    float a0 = 0.0f, a1 = 0.0f, a2 = 0.0f, a3 = 0.0f;
#pragma unroll 8
    for (int d = d0; d < d0 + 64; d += 4) {
        a0 = fmaf(st[d],     w[(size_t)d * KK],       a0);
        a1 = fmaf(st[d + 1], w[(size_t)(d + 1) * KK], a1);
        a2 = fmaf(st[d + 2], w[(size_t)(d + 2) * KK], a2);
        a3 = fmaf(st[d + 3], w[(size_t)(d + 3) * KK], a3);
    }
    sred[dg][kl] = (a0 + a1) + (a2 + a3);
    __syncthreads();
    if (tid < 32) {
        float sacc = 0.0f;
#pragma unroll
        for (int g = 0; g < 8; g++) sacc += sred[g][tid];
        out[b * KK + k0 + tid] = g_vQp[b * KK + k0 + tid] + sacc;
    }
}

// ---------------------------------------------------------------------------
// Launch. Inputs: vI, vQ, Wi, Wq, bq, Wp, bp
// ---------------------------------------------------------------------------
extern "C" void kernel_launch(void* const* d_in, const int* in_sizes, int n_in,
                              void* d_out, int out_size) {
    const float* vI = (const float*)d_in[0];
    const float* vQ = (const float*)d_in[1];
    const float* Wi = (const float*)d_in[2];
    const float* Wq = (const float*)d_in[3];
    const float* bq = (const float*)d_in[4];
    const float* Wp = (const float*)d_in[5];
    // bp shifts scores uniformly -> softmax-invariant; unused.
    float* out = (float*)d_out;

    cudaFuncSetAttribute(scores_mma_kernel,
                         cudaFuncAttributeMaxDynamicSharedMemorySize, SCORES_SMEM);

    {
        dim3 grid(DD / 32, KK / 32);
        dim3 blk(32, 32);
        transpose_wi_kernel<<<grid, blk>>>(Wi);
    }
    {
        dim3 grid(BB, 8);
        vqp_kernel<<<grid, 256>>>(vQ, Wq, bq);
    }
    {
        dim3 grid(NN / M_TILE, BB);  // 16 x 32 = 512 CTAs
        scores_mma_kernel<<<grid, 512, SCORES_SMEM>>>(vI, Wp);
    }
    {
        dim3 grid(BB, 8);
        out_kernel<<<grid, 256>>>(Wi, out);
    }
}